// round 12
// baseline (speedup 1.0000x reference)
#include <cuda_runtime.h>
#include <cuda_fp16.h>
#include <math.h>

// Problem constants
#define BB    4
#define CC    256
#define NN    4096      // h*w = 64*64
#define GG    8
#define NHEAD 4
#define DD    64        // head dim
#define EPSV  1e-5f

// Scratch (device globals: no allocations allowed)
__device__ float  g_xn [(size_t)BB * CC * NN];       // groupnorm output (tf32-rounded)
__device__ float  g_qkv[(size_t)BB * 3 * CC * NN];   // qkv output fp32
__device__ float  g_att[(size_t)BB * CC * NN];       // attention output (tf32-rounded)
__device__ float  g_wq [(size_t)3 * CC * CC];        // qkv_w tf32-rounded
__device__ float  g_wp [(size_t)CC * CC];            // proj_w tf32-rounded
__device__ float  g_stats[BB * GG * 2];              // gn partial sums
__device__ __half g_qT[(size_t)BB * NHEAD * NN * DD];   // Q^T half [bh][tok][d] (prescaled)
__device__ __half g_kT[(size_t)BB * NHEAD * NN * DD];   // K^T half [bh][tok][d]
__device__ __half g_vh[(size_t)BB * NHEAD * DD * NN];   // V half [bh][d][tok]

__device__ __forceinline__ unsigned f2tf32(float x) {
    unsigned r;
    asm("cvt.rna.tf32.f32 %0, %1;" : "=r"(r) : "f"(x));
    return r;
}
__device__ __forceinline__ float tf32r(float x) {
    return __uint_as_float(f2tf32(x));
}

__device__ __forceinline__ void mma_tf32(float c[4], const unsigned a[4],
                                         unsigned b0, unsigned b1) {
    asm volatile(
        "mma.sync.aligned.m16n8k8.row.col.f32.tf32.tf32.f32 "
        "{%0,%1,%2,%3}, {%4,%5,%6,%7}, {%8,%9}, {%0,%1,%2,%3};"
        : "+f"(c[0]), "+f"(c[1]), "+f"(c[2]), "+f"(c[3])
        : "r"(a[0]), "r"(a[1]), "r"(a[2]), "r"(a[3]), "r"(b0), "r"(b1));
}

__device__ __forceinline__ void mma_f16(float c[4], const unsigned a[4],
                                        unsigned b0, unsigned b1) {
    asm volatile(
        "mma.sync.aligned.m16n8k16.row.col.f32.f16.f16.f32 "
        "{%0,%1,%2,%3}, {%4,%5,%6,%7}, {%8,%9}, {%0,%1,%2,%3};"
        : "+f"(c[0]), "+f"(c[1]), "+f"(c[2]), "+f"(c[3])
        : "r"(a[0]), "r"(a[1]), "r"(a[2]), "r"(a[3]), "r"(b0), "r"(b1));
}

__device__ __forceinline__ void cpasync16(unsigned saddr, const void* gptr) {
    asm volatile("cp.async.cg.shared.global [%0], [%1], 16;"
                 :: "r"(saddr), "l"(gptr));
}
__device__ __forceinline__ void cp_commit() {
    asm volatile("cp.async.commit_group;");
}
template <int N>
__device__ __forceinline__ void cp_wait() {
    asm volatile("cp.async.wait_group %0;" :: "n"(N));
}
__device__ __forceinline__ unsigned packh2(float a, float b) {
    __half2 h = __floats2half2_rn(a, b);
    return *(const unsigned*)&h;
}

// ---------------------------------------------------------------------------
// Weight conversion (+ zero gn stats)
// ---------------------------------------------------------------------------
__global__ __launch_bounds__(256) void wconv_kernel(
    const float* __restrict__ qkv_w, const float* __restrict__ proj_w,
    float* __restrict__ wq, float* __restrict__ wp)
{
    int i = blockIdx.x * 256 + threadIdx.x;
    if (blockIdx.x == 0 && threadIdx.x < BB * GG * 2) g_stats[threadIdx.x] = 0.f;
    if (i < 3 * CC * CC) wq[i] = tf32r(qkv_w[i]);
    if (i < CC * CC)     wp[i] = tf32r(proj_w[i]);
}

// ---------------------------------------------------------------------------
// GroupNorm stats: 8 blocks per (b,g), atomic partial sums.
// ---------------------------------------------------------------------------
__global__ __launch_bounds__(256) void gn_stats_kernel(const float* __restrict__ x)
{
    const int bg   = blockIdx.x >> 3;
    const int part = blockIdx.x & 7;
    const float4* xp = (const float4*)(x) + (size_t)bg * 32768 + part * 4096;

    float s = 0.f, ss = 0.f;
    #pragma unroll
    for (int i = 0; i < 16; i++) {
        float4 v = xp[i * 256 + threadIdx.x];
        s  += v.x + v.y + v.z + v.w;
        ss += v.x * v.x + v.y * v.y + v.z * v.z + v.w * v.w;
    }
    __shared__ float rs[8], rss[8];
    #pragma unroll
    for (int o = 16; o; o >>= 1) {
        s  += __shfl_down_sync(0xffffffffu, s,  o);
        ss += __shfl_down_sync(0xffffffffu, ss, o);
    }
    int wid = threadIdx.x >> 5, lid = threadIdx.x & 31;
    if (!lid) { rs[wid] = s; rss[wid] = ss; }
    __syncthreads();
    if (threadIdx.x < 8) {
        s = rs[threadIdx.x]; ss = rss[threadIdx.x];
        #pragma unroll
        for (int o = 4; o; o >>= 1) {
            s  += __shfl_down_sync(0xffu, s,  o);
            ss += __shfl_down_sync(0xffu, ss, o);
        }
        if (threadIdx.x == 0) {
            atomicAdd(&g_stats[bg * 2],     s);
            atomicAdd(&g_stats[bg * 2 + 1], ss);
        }
    }
}

// ---------------------------------------------------------------------------
// GroupNorm normalize: wide grid, tf32-rounded output.
// ---------------------------------------------------------------------------
__global__ __launch_bounds__(256) void gn_norm_kernel(
    const float* __restrict__ x, const float* __restrict__ gw,
    const float* __restrict__ gb, float* __restrict__ xn)
{
    const float4* xp = (const float4*)x;
    float4* op = (float4*)xn;
    #pragma unroll
    for (int i = 0; i < 16; i++) {
        int f = blockIdx.x * 4096 + i * 256 + threadIdx.x;
        int ch = f >> 10;
        int c  = ch & 255;
        int bg = ((ch >> 8) << 3) | (c >> 5);
        float s  = g_stats[bg * 2];
        float ss = g_stats[bg * 2 + 1];
        float mean = s * (1.f / 131072.f);
        float var  = ss * (1.f / 131072.f) - mean * mean;
        float rstd = rsqrtf(var + EPSV);
        float a  = gw[c] * rstd;
        float bb = gb[c] - mean * a;
        float4 v = xp[f];
        v.x = tf32r(v.x * a + bb); v.y = tf32r(v.y * a + bb);
        v.z = tf32r(v.z * a + bb); v.w = tf32r(v.w * a + bb);
        op[f] = v;
    }
}

// ---------------------------------------------------------------------------
// tf32 MMA GEMM with cp.async double-buffering (unchanged).
// ---------------------------------------------------------------------------
__global__ __launch_bounds__(256) void gemm_tf32_kernel(
    const float* __restrict__ A, const float* __restrict__ Bm,
    const float* __restrict__ bias, const float* __restrict__ res,
    float* __restrict__ C, int M, int round_out)
{
    __shared__ float As[2][64][36];
    __shared__ float Bs[2][32][132];
    const unsigned as_u = (unsigned)__cvta_generic_to_shared(&As[0][0][0]);
    const unsigned bs_u = (unsigned)__cvta_generic_to_shared(&Bs[0][0][0]);

    const int bz = blockIdx.z;
    const float* Bp = Bm + (size_t)bz * CC * NN;
    float*       Cp = C  + (size_t)bz * M * NN;
    const float* Rp = res ? res + (size_t)bz * M * NN : nullptr;

    const int n0 = blockIdx.x * 128;
    const int m0 = blockIdx.y * 64;
    const int tid = threadIdx.x;
    const int w = tid >> 5, lane = tid & 31;
    const int g = lane >> 2, tig = lane & 3;
    const int wm = (w >> 2) * 32;
    const int wn = (w & 3) * 32;

    const int ar = tid >> 3, ac4 = tid & 7;
    const int br = tid >> 5, bc4 = tid & 31;

    #define GEMM_ISSUE(K0, BUF)                                              \
    {                                                                        \
        unsigned ab = as_u + (unsigned)((BUF) * 64 * 36 * 4);                \
        unsigned bb = bs_u + (unsigned)((BUF) * 32 * 132 * 4);               \
        _Pragma("unroll")                                                    \
        for (int i = 0; i < 2; i++) {                                        \
            int r = ar + i * 32;                                             \
            cpasync16(ab + (unsigned)((r * 36 + ac4 * 4) * 4),               \
                      &A[(size_t)(m0 + r) * CC + (K0) + ac4 * 4]);           \
        }                                                                    \
        _Pragma("unroll")                                                    \
        for (int i = 0; i < 4; i++) {                                        \
            int r = br + i * 8;                                              \
            cpasync16(bb + (unsigned)((r * 132 + bc4 * 4) * 4),              \
                      &Bp[(size_t)((K0) + r) * NN + n0 + bc4 * 4]);          \
        }                                                                    \
        cp_commit();                                                         \
    }

    GEMM_ISSUE(0, 0)
    GEMM_ISSUE(32, 1)

    float acc[2][4][4] = {};

    for (int kt = 0; kt < 8; kt++) {
        const int cur = kt & 1;
        if (kt < 7) cp_wait<1>(); else cp_wait<0>();
        __syncthreads();

        #pragma unroll
        for (int ks = 0; ks < 4; ks++) {
            unsigned a[2][4];
            #pragma unroll
            for (int mt = 0; mt < 2; mt++) {
                a[mt][0] = __float_as_uint(As[cur][wm + mt * 16 + g    ][ks * 8 + tig]);
                a[mt][1] = __float_as_uint(As[cur][wm + mt * 16 + g + 8][ks * 8 + tig]);
                a[mt][2] = __float_as_uint(As[cur][wm + mt * 16 + g    ][ks * 8 + tig + 4]);
                a[mt][3] = __float_as_uint(As[cur][wm + mt * 16 + g + 8][ks * 8 + tig + 4]);
            }
            #pragma unroll
            for (int nt = 0; nt < 4; nt++) {
                unsigned b0 = __float_as_uint(Bs[cur][ks * 8 + tig    ][wn + nt * 8 + g]);
                unsigned b1 = __float_as_uint(Bs[cur][ks * 8 + tig + 4][wn + nt * 8 + g]);
                mma_tf32(acc[0][nt], a[0], b0, b1);
                mma_tf32(acc[1][nt], a[1], b0, b1);
            }
        }
        __syncthreads();

        if (kt < 6) GEMM_ISSUE((kt + 2) * 32, cur)
    }
    #undef GEMM_ISSUE

    #pragma unroll
    for (int mt = 0; mt < 2; mt++) {
        #pragma unroll
        for (int half = 0; half < 2; half++) {
            const int m = m0 + wm + mt * 16 + g + half * 8;
            const float bi = bias[m];
            #pragma unroll
            for (int nt = 0; nt < 4; nt++) {
                float v0 = acc[mt][nt][half * 2 + 0] + bi;
                float v1 = acc[mt][nt][half * 2 + 1] + bi;
                const size_t off = (size_t)m * NN + n0 + wn + nt * 8 + 2 * tig;
                if (Rp) {
                    float2 r = *(const float2*)&Rp[off];
                    v0 += r.x; v1 += r.y;
                }
                if (round_out) { v0 = tf32r(v0); v1 = tf32r(v1); }
                *(float2*)&Cp[off] = make_float2(v0, v1);
            }
        }
    }
}

// ---------------------------------------------------------------------------
// Pack kernel: qkv fp32 -> qT/kT half [bh][tok][d] (Q prescaled 0.125) and
// vh half [bh][d][tok]. One block per (bh, 64-token tile), 256 threads.
// ---------------------------------------------------------------------------
__global__ __launch_bounds__(256) void pack_kernel(
    const float* __restrict__ qkv, __half* __restrict__ qT,
    __half* __restrict__ kT, __half* __restrict__ vh)
{
    __shared__ __half ts[64][66];
    const int tid  = threadIdx.x;
    const int bh   = blockIdx.y;
    const int b    = bh >> 2;
    const int hh   = bh & 3;
    const int tokb = blockIdx.x * 64;
    const float* base = qkv + (size_t)b * (3 * CC) * NN;

    #pragma unroll
    for (int which = 0; which < 2; which++) {   // 0: Q, 1: K
        const float* src = base + (size_t)(which * CC + hh * DD) * NN;
        const float scale = which ? 1.f : 0.125f;
        __half* dst = (which ? kT : qT) + ((size_t)bh * NN + tokb) * DD;

        #pragma unroll
        for (int j = 0; j < 4; j++) {
            int idx = tid + j * 256;
            int d = idx >> 4, c4 = idx & 15;
            float4 v = *(const float4*)&src[(size_t)d * NN + tokb + c4 * 4];
            *(__half2*)&ts[d][c4 * 4]     = __floats2half2_rn(v.x * scale, v.y * scale);
            *(__half2*)&ts[d][c4 * 4 + 2] = __floats2half2_rn(v.z * scale, v.w * scale);
        }
        __syncthreads();
        #pragma unroll
        for (int j = 0; j < 4; j++) {
            int idx = tid + j * 256;
            int t = idx >> 4, dc = idx & 15;
            __half2 p01 = __halves2half2(ts[dc * 4 + 0][t], ts[dc * 4 + 1][t]);
            __half2 p23 = __halves2half2(ts[dc * 4 + 2][t], ts[dc * 4 + 3][t]);
            uint2 u;
            u.x = *(const unsigned*)&p01;
            u.y = *(const unsigned*)&p23;
            *(uint2*)&dst[(size_t)t * DD + dc * 4] = u;
        }
        __syncthreads();
    }

    // V: direct convert, natural layout
    const float* vsrc = base + (size_t)(2 * CC + hh * DD) * NN;
    __half* vdst = vh + (size_t)bh * DD * NN + tokb;
    #pragma unroll
    for (int j = 0; j < 4; j++) {
        int idx = tid + j * 256;
        int d = idx >> 4, c4 = idx & 15;
        float4 v = *(const float4*)&vsrc[(size_t)d * NN + tokb + c4 * 4];
        __half2 p01 = __floats2half2_rn(v.x, v.y);
        __half2 p23 = __floats2half2_rn(v.z, v.w);
        uint2 u;
        u.x = *(const unsigned*)&p01;
        u.y = *(const unsigned*)&p23;
        *(uint2*)&vdst[(size_t)d * NN + c4 * 4] = u;
    }
}

// ---------------------------------------------------------------------------
// Flash attention, fp16 m16n8k16, BM=128 (8 warps x 16 rows), cp.async
// double-buffered K/V, identity P C->A mapping.
// One block = (bh, 128-query tile), 256 threads.
// ---------------------------------------------------------------------------
#define HPAD 72                             // halves per smem row
#define TILE_H (64 * HPAD)                  // halves per K/V tile
#define ATTN_SMEM_BYTES (4 * TILE_H * 2)    // 36864 B

__global__ void __launch_bounds__(256, 2) attn_h_kernel(
    const __half* __restrict__ qT, const __half* __restrict__ kT,
    const __half* __restrict__ vh, float* __restrict__ out)
{
    extern __shared__ __half hsm[];
    __half* Ks = hsm;                     // [2][64][HPAD]  (kT: [token][d])
    __half* Vs = hsm + 2 * TILE_H;        // [2][64][HPAD]  (v:  [d][token])
    const unsigned ks_u = (unsigned)__cvta_generic_to_shared(Ks);
    const unsigned vs_u = (unsigned)__cvta_generic_to_shared(Vs);

    const int tid  = threadIdx.x;
    const int w    = tid >> 5;            // 0..7
    const int lane = tid & 31;
    const int g    = lane >> 2;
    const int tig  = lane & 3;

    const int bh = blockIdx.y;
    const int qb = blockIdx.x * 128;

    const __half* qTp = qT + ((size_t)bh * NN + qb) * DD;
    const __half* kTp = kT + (size_t)bh * NN * DD;
    const __half* vp  = vh + (size_t)bh * DD * NN;

    // --- Stage Q tile (128 tok x 64 d halves) into Ks (both buffers) ---
    #pragma unroll
    for (int i = 0; i < 4; i++) {
        int lin = tid + i * 256;          // 0..1023
        int row = lin >> 3, c = lin & 7;  // row 0..127
        cpasync16(ks_u + (unsigned)((row * HPAD + c * 8) * 2),
                  qTp + (size_t)row * DD + c * 8);
    }
    cp_commit();
    cp_wait<0>();
    __syncthreads();

    unsigned qa[4][4];
    {
        const int m0 = w * 16 + g;        // 0..127
        #pragma unroll
        for (int kt = 0; kt < 4; kt++) {
            qa[kt][0] = *(const unsigned*)&Ks[(m0    ) * HPAD + kt * 16 + 2 * tig];
            qa[kt][1] = *(const unsigned*)&Ks[(m0 + 8) * HPAD + kt * 16 + 2 * tig];
            qa[kt][2] = *(const unsigned*)&Ks[(m0    ) * HPAD + kt * 16 + 2 * tig + 8];
            qa[kt][3] = *(const unsigned*)&Ks[(m0 + 8) * HPAD + kt * 16 + 2 * tig + 8];
        }
    }
    __syncthreads();

    // --- Pipeline prologue: tiles 0, 1 ---
    #pragma unroll
    for (int pre = 0; pre < 2; pre++) {
        int jt = pre * 64;
        unsigned kb = ks_u + (unsigned)(pre * TILE_H * 2);
        unsigned vb = vs_u + (unsigned)(pre * TILE_H * 2);
        #pragma unroll
        for (int i = 0; i < 2; i++) {
            int lin = tid + i * 256;      // 0..511
            int row = lin >> 3, c = lin & 7;
            cpasync16(kb + (unsigned)((row * HPAD + c * 8) * 2),
                      kTp + (size_t)(jt + row) * DD + c * 8);
            cpasync16(vb + (unsigned)((row * HPAD + c * 8) * 2),
                      vp + (size_t)row * NN + jt + c * 8);
        }
        cp_commit();
    }

    float O[8][4];
    #pragma unroll
    for (int t = 0; t < 8; t++)
        #pragma unroll
        for (int r = 0; r < 4; r++) O[t][r] = 0.f;
    float m0r = -INFINITY, m1r = -INFINITY, l0 = 0.f, l1 = 0.f;

    for (int it = 0; it < 64; it++) {
        const int cur = it & 1;
        const __half* Kc = Ks + cur * TILE_H;
        const __half* Vc = Vs + cur * TILE_H;

        if (it < 63) cp_wait<1>(); else cp_wait<0>();
        __syncthreads();

        // --- S = Q K^T : 8 n-tiles x 4 k16-steps ---
        float sc[8][4];
        #pragma unroll
        for (int t = 0; t < 8; t++) {
            sc[t][0] = sc[t][1] = sc[t][2] = sc[t][3] = 0.f;
            #pragma unroll
            for (int kt = 0; kt < 4; kt++) {
                unsigned b0 = *(const unsigned*)&Kc[(t * 8 + g) * HPAD + kt * 16 + 2 * tig];
                unsigned b1 = *(const unsigned*)&Kc[(t * 8 + g) * HPAD + kt * 16 + 2 * tig + 8];
                mma_f16(sc[t], qa[kt], b0, b1);
            }
        }

        // --- Online softmax (c0,c1 = row g; c2,c3 = row g+8) ---
        float ml0 = -INFINITY, ml1 = -INFINITY;
        #pragma unroll
        for (int t = 0; t < 8; t++) {
            ml0 = fmaxf(ml0, fmaxf(sc[t][0], sc[t][1]));
            ml1 = fmaxf(ml1, fmaxf(sc[t][2], sc[t][3]));
        }
        ml0 = fmaxf(ml0, __shfl_xor_sync(0xffffffffu, ml0, 1));
        ml0 = fmaxf(ml0, __shfl_xor_sync(0xffffffffu, ml0, 2));
        ml1 = fmaxf(ml1, __shfl_xor_sync(0xffffffffu, ml1, 1));
        ml1 = fmaxf(ml1, __shfl_xor_sync(0xffffffffu, ml1, 2));

        const float mn0 = fmaxf(m0r, ml0);
        const float mn1 = fmaxf(m1r, ml1);
        const float corr0 = __expf(m0r - mn0);
        const float corr1 = __expf(m1r - mn1);
        m0r = mn0; m1r = mn1;

        // exp + pack to half2
        unsigned pe[8], po[8];
        float ls0 = 0.f, ls1 = 0.f;
        #pragma unroll
        for (int t = 0; t < 8; t++) {
            float p0 = __expf(sc[t][0] - mn0);
            float p1 = __expf(sc[t][1] - mn0);
            float p2 = __expf(sc[t][2] - mn1);
            float p3 = __expf(sc[t][3] - mn1);
            ls0 += p0 + p1; ls1 += p2 + p3;
            pe[t] = packh2(p0, p1);
            po[t] = packh2(p2, p3);
        }
        ls0 += __shfl_xor_sync(0xffffffffu, ls0, 1);
        ls0 += __shfl_xor_sync(0xffffffffu, ls0, 2);
        ls1 += __shfl_xor_sync(0xffffffffu, ls1, 1);
        ls1 += __shfl_xor_sync(0xffffffffu, ls1, 2);
        l0 = l0 * corr0 + ls0;
        l1 = l1 * corr1 + ls1;

        #pragma unroll
        for (int t = 0; t < 8; t++) {
            O[t][0] *= corr0; O[t][1] *= corr0;
            O[t][2] *= corr1; O[t][3] *= corr1;
        }

        // --- O += P V^T : identity C->A fragment mapping ---
        #pragma unroll
        for (int kn = 0; kn < 4; kn++) {
            unsigned pa[4];
            pa[0] = pe[2 * kn];
            pa[1] = po[2 * kn];
            pa[2] = pe[2 * kn + 1];
            pa[3] = po[2 * kn + 1];
            #pragma unroll
            for (int dt = 0; dt < 8; dt++) {
                unsigned b0 = *(const unsigned*)&Vc[(dt * 8 + g) * HPAD + kn * 16 + 2 * tig];
                unsigned b1 = *(const unsigned*)&Vc[(dt * 8 + g) * HPAD + kn * 16 + 2 * tig + 8];
                mma_f16(O[dt], pa, b0, b1);
            }
        }

        __syncthreads();

        if (it < 62) {
            int jt = (it + 2) * 64;
            unsigned kb = ks_u + (unsigned)(cur * TILE_H * 2);
            unsigned vb = vs_u + (unsigned)(cur * TILE_H * 2);
            #pragma unroll
            for (int i = 0; i < 2; i++) {
                int lin = tid + i * 256;
                int row = lin >> 3, c = lin & 7;
                cpasync16(kb + (unsigned)((row * HPAD + c * 8) * 2),
                          kTp + (size_t)(jt + row) * DD + c * 8);
                cpasync16(vb + (unsigned)((row * HPAD + c * 8) * 2),
                          vp + (size_t)row * NN + jt + c * 8);
            }
            cp_commit();
        }
    }

    // --- Epilogue: normalize + round + store [d][tok] fp32 ---
    const float inv0 = 1.f / l0;
    const float inv1 = 1.f / l1;
    const int b  = bh >> 2;
    const int hh = bh & 3;
    float* op = out + ((size_t)b * CC + hh * DD) * NN;
    const int tok0 = qb + w * 16 + g;
    const int tok1 = tok0 + 8;
    #pragma unroll
    for (int dt = 0; dt < 8; dt++) {
        int d = dt * 8 + 2 * tig;
        op[(size_t)d * NN + tok0]       = tf32r(O[dt][0] * inv0);
        op[(size_t)(d + 1) * NN + tok0] = tf32r(O[dt][1] * inv0);
        op[(size_t)d * NN + tok1]       = tf32r(O[dt][2] * inv1);
        op[(size_t)(d + 1) * NN + tok1] = tf32r(O[dt][3] * inv1);
    }
}

// ---------------------------------------------------------------------------
// Launch
// ---------------------------------------------------------------------------
extern "C" void kernel_launch(void* const* d_in, const int* in_sizes, int n_in,
                              void* d_out, int out_size)
{
    const float* x      = (const float*)d_in[0];
    const float* gn_w   = (const float*)d_in[1];
    const float* gn_b   = (const float*)d_in[2];
    const float* qkv_w  = (const float*)d_in[3];
    const float* qkv_b  = (const float*)d_in[4];
    const float* proj_w = (const float*)d_in[5];
    const float* proj_b = (const float*)d_in[6];
    float* out = (float*)d_out;

    void *p_xn, *p_qkv, *p_att, *p_wq, *p_wp, *p_qT, *p_kT, *p_vh;
    cudaGetSymbolAddress(&p_xn,  g_xn);
    cudaGetSymbolAddress(&p_qkv, g_qkv);
    cudaGetSymbolAddress(&p_att, g_att);
    cudaGetSymbolAddress(&p_wq,  g_wq);
    cudaGetSymbolAddress(&p_wp,  g_wp);
    cudaGetSymbolAddress(&p_qT,  g_qT);
    cudaGetSymbolAddress(&p_kT,  g_kT);
    cudaGetSymbolAddress(&p_vh,  g_vh);
    float*  xn  = (float*)p_xn;
    float*  qkv = (float*)p_qkv;
    float*  att = (float*)p_att;
    float*  wq  = (float*)p_wq;
    float*  wp  = (float*)p_wp;
    __half* qT  = (__half*)p_qT;
    __half* kT  = (__half*)p_kT;
    __half* vh  = (__half*)p_vh;

    cudaFuncSetAttribute(attn_h_kernel,
                         cudaFuncAttributeMaxDynamicSharedMemorySize,
                         ATTN_SMEM_BYTES);

    // 0. Round weights to tf32 (also zeros gn stats)
    wconv_kernel<<<(3 * CC * CC + 255) / 256, 256>>>(qkv_w, proj_w, wq, wp);

    // 1. GroupNorm: stats (atomic) then normalize
    gn_stats_kernel<<<BB * GG * 8, 256>>>(x);
    gn_norm_kernel<<<BB * CC * NN / 4 / 4096, 256>>>(x, gn_w, gn_b, xn);

    // 2. QKV GEMM (tf32 tensor, cp.async pipeline)
    {
        dim3 grid(NN / 128, (3 * CC) / 64, BB);
        gemm_tf32_kernel<<<grid, 256>>>(wq, xn, qkv_b, nullptr, qkv, 3 * CC, 0);
    }

    // 2b. Pack: qkv fp32 -> qT/kT (transposed half) + vh (natural half)
    {
        dim3 grid(NN / 64, BB * NHEAD);
        pack_kernel<<<grid, 256>>>(qkv, qT, kT, vh);
    }

    // 3. Attention (fp16 tensor, BM=128, cp.async pipeline)
    {
        dim3 grid(NN / 128, BB * NHEAD);
        attn_h_kernel<<<grid, 256, ATTN_SMEM_BYTES>>>(qT, kT, vh, att);
    }

    // 4. Proj GEMM (tf32 tensor, cp.async pipeline) + bias + residual
    {
        dim3 grid(NN / 128, CC / 64, BB);
        gemm_tf32_kernel<<<grid, 256>>>(wp, att, proj_b, x, out, CC, 0);
    }
}

// round 13
// speedup vs baseline: 1.0799x; 1.0799x over previous
#include <cuda_runtime.h>
#include <cuda_fp16.h>
#include <math.h>

// Problem constants
#define BB    4
#define CC    256
#define NN    4096      // h*w = 64*64
#define GG    8
#define NHEAD 4
#define DD    64        // head dim
#define EPSV  1e-5f

// Scratch (device globals: no allocations allowed)
__device__ float  g_xn [(size_t)BB * CC * NN];       // groupnorm output (tf32-rounded)
__device__ float  g_att[(size_t)BB * CC * NN];       // attention output (tf32-rounded)
__device__ float  g_wq [(size_t)3 * CC * CC];        // qkv_w tf32-rounded
__device__ float  g_wp [(size_t)CC * CC];            // proj_w tf32-rounded
__device__ float  g_stats[BB * GG * 2];              // gn partial sums
__device__ __half g_qT[(size_t)BB * NHEAD * NN * DD];   // Q^T half [bh][tok][d] (prescaled)
__device__ __half g_kT[(size_t)BB * NHEAD * NN * DD];   // K^T half [bh][tok][d]
__device__ __half g_vh[(size_t)BB * NHEAD * DD * NN];   // V half [bh][d][tok]

__device__ __forceinline__ unsigned f2tf32(float x) {
    unsigned r;
    asm("cvt.rna.tf32.f32 %0, %1;" : "=r"(r) : "f"(x));
    return r;
}
__device__ __forceinline__ float tf32r(float x) {
    return __uint_as_float(f2tf32(x));
}

__device__ __forceinline__ void mma_tf32(float c[4], const unsigned a[4],
                                         unsigned b0, unsigned b1) {
    asm volatile(
        "mma.sync.aligned.m16n8k8.row.col.f32.tf32.tf32.f32 "
        "{%0,%1,%2,%3}, {%4,%5,%6,%7}, {%8,%9}, {%0,%1,%2,%3};"
        : "+f"(c[0]), "+f"(c[1]), "+f"(c[2]), "+f"(c[3])
        : "r"(a[0]), "r"(a[1]), "r"(a[2]), "r"(a[3]), "r"(b0), "r"(b1));
}

__device__ __forceinline__ void mma_f16(float c[4], const unsigned a[4],
                                        unsigned b0, unsigned b1) {
    asm volatile(
        "mma.sync.aligned.m16n8k16.row.col.f32.f16.f16.f32 "
        "{%0,%1,%2,%3}, {%4,%5,%6,%7}, {%8,%9}, {%0,%1,%2,%3};"
        : "+f"(c[0]), "+f"(c[1]), "+f"(c[2]), "+f"(c[3])
        : "r"(a[0]), "r"(a[1]), "r"(a[2]), "r"(a[3]), "r"(b0), "r"(b1));
}

__device__ __forceinline__ void cpasync16(unsigned saddr, const void* gptr) {
    asm volatile("cp.async.cg.shared.global [%0], [%1], 16;"
                 :: "r"(saddr), "l"(gptr));
}
__device__ __forceinline__ void cp_commit() {
    asm volatile("cp.async.commit_group;");
}
template <int N>
__device__ __forceinline__ void cp_wait() {
    asm volatile("cp.async.wait_group %0;" :: "n"(N));
}
__device__ __forceinline__ unsigned packh2(float a, float b) {
    __half2 h = __floats2half2_rn(a, b);
    return *(const unsigned*)&h;
}

// ---------------------------------------------------------------------------
// Weight conversion (+ zero gn stats)
// ---------------------------------------------------------------------------
__global__ __launch_bounds__(256) void wconv_kernel(
    const float* __restrict__ qkv_w, const float* __restrict__ proj_w,
    float* __restrict__ wq, float* __restrict__ wp)
{
    int i = blockIdx.x * 256 + threadIdx.x;
    if (blockIdx.x == 0 && threadIdx.x < BB * GG * 2) g_stats[threadIdx.x] = 0.f;
    if (i < 3 * CC * CC) wq[i] = tf32r(qkv_w[i]);
    if (i < CC * CC)     wp[i] = tf32r(proj_w[i]);
}

// ---------------------------------------------------------------------------
// GroupNorm stats: 8 blocks per (b,g), atomic partial sums.
// ---------------------------------------------------------------------------
__global__ __launch_bounds__(256) void gn_stats_kernel(const float* __restrict__ x)
{
    const int bg   = blockIdx.x >> 3;
    const int part = blockIdx.x & 7;
    const float4* xp = (const float4*)(x) + (size_t)bg * 32768 + part * 4096;

    float s = 0.f, ss = 0.f;
    #pragma unroll
    for (int i = 0; i < 16; i++) {
        float4 v = xp[i * 256 + threadIdx.x];
        s  += v.x + v.y + v.z + v.w;
        ss += v.x * v.x + v.y * v.y + v.z * v.z + v.w * v.w;
    }
    __shared__ float rs[8], rss[8];
    #pragma unroll
    for (int o = 16; o; o >>= 1) {
        s  += __shfl_down_sync(0xffffffffu, s,  o);
        ss += __shfl_down_sync(0xffffffffu, ss, o);
    }
    int wid = threadIdx.x >> 5, lid = threadIdx.x & 31;
    if (!lid) { rs[wid] = s; rss[wid] = ss; }
    __syncthreads();
    if (threadIdx.x < 8) {
        s = rs[threadIdx.x]; ss = rss[threadIdx.x];
        #pragma unroll
        for (int o = 4; o; o >>= 1) {
            s  += __shfl_down_sync(0xffu, s,  o);
            ss += __shfl_down_sync(0xffu, ss, o);
        }
        if (threadIdx.x == 0) {
            atomicAdd(&g_stats[bg * 2],     s);
            atomicAdd(&g_stats[bg * 2 + 1], ss);
        }
    }
}

// ---------------------------------------------------------------------------
// GroupNorm normalize: wide grid, tf32-rounded output.
// ---------------------------------------------------------------------------
__global__ __launch_bounds__(256) void gn_norm_kernel(
    const float* __restrict__ x, const float* __restrict__ gw,
    const float* __restrict__ gb, float* __restrict__ xn)
{
    const float4* xp = (const float4*)x;
    float4* op = (float4*)xn;
    #pragma unroll
    for (int i = 0; i < 16; i++) {
        int f = blockIdx.x * 4096 + i * 256 + threadIdx.x;
        int ch = f >> 10;
        int c  = ch & 255;
        int bg = ((ch >> 8) << 3) | (c >> 5);
        float s  = g_stats[bg * 2];
        float ss = g_stats[bg * 2 + 1];
        float mean = s * (1.f / 131072.f);
        float var  = ss * (1.f / 131072.f) - mean * mean;
        float rstd = rsqrtf(var + EPSV);
        float a  = gw[c] * rstd;
        float bb = gb[c] - mean * a;
        float4 v = xp[f];
        v.x = tf32r(v.x * a + bb); v.y = tf32r(v.y * a + bb);
        v.z = tf32r(v.z * a + bb); v.w = tf32r(v.w * a + bb);
        op[f] = v;
    }
}

// ---------------------------------------------------------------------------
// QKV GEMM (tf32 MMA, cp.async double-buffered) with FUSED pack epilogue:
// each block covers one (q/k/v, head) x 64 d x 128 tokens, and writes
// half outputs directly: Q/K -> [tok][d] via smem transpose, V -> [d][tok].
// ---------------------------------------------------------------------------
__global__ __launch_bounds__(256) void gemm_qkv_kernel(
    const float* __restrict__ A, const float* __restrict__ Bm,
    const float* __restrict__ bias,
    __half* __restrict__ qT, __half* __restrict__ kT, __half* __restrict__ vh)
{
    __shared__ float As[2][64][36];
    __shared__ float Bs[2][32][132];
    const unsigned as_u = (unsigned)__cvta_generic_to_shared(&As[0][0][0]);
    const unsigned bs_u = (unsigned)__cvta_generic_to_shared(&Bs[0][0][0]);

    const int bz = blockIdx.z;
    const float* Bp = Bm + (size_t)bz * CC * NN;

    const int n0 = blockIdx.x * 128;
    const int m0 = blockIdx.y * 64;
    const int tid = threadIdx.x;
    const int w = tid >> 5, lane = tid & 31;
    const int g = lane >> 2, tig = lane & 3;
    const int wm = (w >> 2) * 32;
    const int wn = (w & 3) * 32;

    const int ar = tid >> 3, ac4 = tid & 7;
    const int br = tid >> 5, bc4 = tid & 31;

    #define GEMM_ISSUE(K0, BUF)                                              \
    {                                                                        \
        unsigned ab = as_u + (unsigned)((BUF) * 64 * 36 * 4);                \
        unsigned bb = bs_u + (unsigned)((BUF) * 32 * 132 * 4);               \
        _Pragma("unroll")                                                    \
        for (int i = 0; i < 2; i++) {                                        \
            int r = ar + i * 32;                                             \
            cpasync16(ab + (unsigned)((r * 36 + ac4 * 4) * 4),               \
                      &A[(size_t)(m0 + r) * CC + (K0) + ac4 * 4]);           \
        }                                                                    \
        _Pragma("unroll")                                                    \
        for (int i = 0; i < 4; i++) {                                        \
            int r = br + i * 8;                                              \
            cpasync16(bb + (unsigned)((r * 132 + bc4 * 4) * 4),              \
                      &Bp[(size_t)((K0) + r) * NN + n0 + bc4 * 4]);          \
        }                                                                    \
        cp_commit();                                                         \
    }

    GEMM_ISSUE(0, 0)
    GEMM_ISSUE(32, 1)

    float acc[2][4][4] = {};

    for (int kt = 0; kt < 8; kt++) {
        const int cur = kt & 1;
        if (kt < 7) cp_wait<1>(); else cp_wait<0>();
        __syncthreads();

        #pragma unroll
        for (int ks = 0; ks < 4; ks++) {
            unsigned a[2][4];
            #pragma unroll
            for (int mt = 0; mt < 2; mt++) {
                a[mt][0] = __float_as_uint(As[cur][wm + mt * 16 + g    ][ks * 8 + tig]);
                a[mt][1] = __float_as_uint(As[cur][wm + mt * 16 + g + 8][ks * 8 + tig]);
                a[mt][2] = __float_as_uint(As[cur][wm + mt * 16 + g    ][ks * 8 + tig + 4]);
                a[mt][3] = __float_as_uint(As[cur][wm + mt * 16 + g + 8][ks * 8 + tig + 4]);
            }
            #pragma unroll
            for (int nt = 0; nt < 4; nt++) {
                unsigned b0 = __float_as_uint(Bs[cur][ks * 8 + tig    ][wn + nt * 8 + g]);
                unsigned b1 = __float_as_uint(Bs[cur][ks * 8 + tig + 4][wn + nt * 8 + g]);
                mma_tf32(acc[0][nt], a[0], b0, b1);
                mma_tf32(acc[1][nt], a[1], b0, b1);
            }
        }
        __syncthreads();

        if (kt < 6) GEMM_ISSUE((kt + 2) * 32, cur)
    }
    #undef GEMM_ISSUE

    // --- Fused pack epilogue ---
    const int which = m0 >> 8;            // 0=Q, 1=K, 2=V
    const int hh    = (m0 >> 6) & 3;
    const int bh    = bz * NHEAD + hh;
    const float scale = (which == 0) ? 0.125f : 1.f;

    if (which == 2) {
        // V: natural [d][tok] layout, direct half2 stores
        #pragma unroll
        for (int mt = 0; mt < 2; mt++) {
            #pragma unroll
            for (int half = 0; half < 2; half++) {
                const int d = wm + mt * 16 + g + half * 8;
                const float bi = bias[m0 + d];
                #pragma unroll
                for (int nt = 0; nt < 4; nt++) {
                    float v0 = acc[mt][nt][half * 2 + 0] + bi;
                    float v1 = acc[mt][nt][half * 2 + 1] + bi;
                    const size_t off = (size_t)(bh * DD + d) * NN + n0 + wn + nt * 8 + 2 * tig;
                    *(__half2*)&vh[off] = __floats2half2_rn(v0, v1);
                }
            }
        }
    } else {
        // Q/K: transpose through smem (reuse As as [128][72] halves = 18432 B)
        __half* tsh = (__half*)&As[0][0][0];
        #pragma unroll
        for (int mt = 0; mt < 2; mt++) {
            #pragma unroll
            for (int half = 0; half < 2; half++) {
                const int d = wm + mt * 16 + g + half * 8;
                const float bi = bias[m0 + d];
                #pragma unroll
                for (int nt = 0; nt < 4; nt++) {
                    float v0 = (acc[mt][nt][half * 2 + 0] + bi) * scale;
                    float v1 = (acc[mt][nt][half * 2 + 1] + bi) * scale;
                    const int tok = wn + nt * 8 + 2 * tig;
                    tsh[tok * 72 + d]       = __float2half_rn(v0);
                    tsh[(tok + 1) * 72 + d] = __float2half_rn(v1);
                }
            }
        }
        __syncthreads();
        __half* dst = (which ? kT : qT) + ((size_t)bh * NN + n0) * DD;
        #pragma unroll
        for (int i = 0; i < 4; i++) {
            int lin = tid + i * 256;        // 1024 chunks of 8 halves
            int row = lin >> 3, c = lin & 7;
            *(uint4*)&dst[(size_t)row * DD + c * 8] =
                *(const uint4*)&tsh[row * 72 + c * 8];
        }
    }
}

// ---------------------------------------------------------------------------
// Proj GEMM: tf32 MMA with cp.async double-buffering (fp32 out + residual).
// ---------------------------------------------------------------------------
__global__ __launch_bounds__(256) void gemm_tf32_kernel(
    const float* __restrict__ A, const float* __restrict__ Bm,
    const float* __restrict__ bias, const float* __restrict__ res,
    float* __restrict__ C, int M)
{
    __shared__ float As[2][64][36];
    __shared__ float Bs[2][32][132];
    const unsigned as_u = (unsigned)__cvta_generic_to_shared(&As[0][0][0]);
    const unsigned bs_u = (unsigned)__cvta_generic_to_shared(&Bs[0][0][0]);

    const int bz = blockIdx.z;
    const float* Bp = Bm + (size_t)bz * CC * NN;
    float*       Cp = C  + (size_t)bz * M * NN;
    const float* Rp = res + (size_t)bz * M * NN;

    const int n0 = blockIdx.x * 128;
    const int m0 = blockIdx.y * 64;
    const int tid = threadIdx.x;
    const int w = tid >> 5, lane = tid & 31;
    const int g = lane >> 2, tig = lane & 3;
    const int wm = (w >> 2) * 32;
    const int wn = (w & 3) * 32;

    const int ar = tid >> 3, ac4 = tid & 7;
    const int br = tid >> 5, bc4 = tid & 31;

    #define GEMM_ISSUE(K0, BUF)                                              \
    {                                                                        \
        unsigned ab = as_u + (unsigned)((BUF) * 64 * 36 * 4);                \
        unsigned bb = bs_u + (unsigned)((BUF) * 32 * 132 * 4);               \
        _Pragma("unroll")                                                    \
        for (int i = 0; i < 2; i++) {                                        \
            int r = ar + i * 32;                                             \
            cpasync16(ab + (unsigned)((r * 36 + ac4 * 4) * 4),               \
                      &A[(size_t)(m0 + r) * CC + (K0) + ac4 * 4]);           \
        }                                                                    \
        _Pragma("unroll")                                                    \
        for (int i = 0; i < 4; i++) {                                        \
            int r = br + i * 8;                                              \
            cpasync16(bb + (unsigned)((r * 132 + bc4 * 4) * 4),              \
                      &Bp[(size_t)((K0) + r) * NN + n0 + bc4 * 4]);          \
        }                                                                    \
        cp_commit();                                                         \
    }

    GEMM_ISSUE(0, 0)
    GEMM_ISSUE(32, 1)

    float acc[2][4][4] = {};

    for (int kt = 0; kt < 8; kt++) {
        const int cur = kt & 1;
        if (kt < 7) cp_wait<1>(); else cp_wait<0>();
        __syncthreads();

        #pragma unroll
        for (int ks = 0; ks < 4; ks++) {
            unsigned a[2][4];
            #pragma unroll
            for (int mt = 0; mt < 2; mt++) {
                a[mt][0] = __float_as_uint(As[cur][wm + mt * 16 + g    ][ks * 8 + tig]);
                a[mt][1] = __float_as_uint(As[cur][wm + mt * 16 + g + 8][ks * 8 + tig]);
                a[mt][2] = __float_as_uint(As[cur][wm + mt * 16 + g    ][ks * 8 + tig + 4]);
                a[mt][3] = __float_as_uint(As[cur][wm + mt * 16 + g + 8][ks * 8 + tig + 4]);
            }
            #pragma unroll
            for (int nt = 0; nt < 4; nt++) {
                unsigned b0 = __float_as_uint(Bs[cur][ks * 8 + tig    ][wn + nt * 8 + g]);
                unsigned b1 = __float_as_uint(Bs[cur][ks * 8 + tig + 4][wn + nt * 8 + g]);
                mma_tf32(acc[0][nt], a[0], b0, b1);
                mma_tf32(acc[1][nt], a[1], b0, b1);
            }
        }
        __syncthreads();

        if (kt < 6) GEMM_ISSUE((kt + 2) * 32, cur)
    }
    #undef GEMM_ISSUE

    #pragma unroll
    for (int mt = 0; mt < 2; mt++) {
        #pragma unroll
        for (int half = 0; half < 2; half++) {
            const int m = m0 + wm + mt * 16 + g + half * 8;
            const float bi = bias[m];
            #pragma unroll
            for (int nt = 0; nt < 4; nt++) {
                float v0 = acc[mt][nt][half * 2 + 0] + bi;
                float v1 = acc[mt][nt][half * 2 + 1] + bi;
                const size_t off = (size_t)m * NN + n0 + wn + nt * 8 + 2 * tig;
                float2 r = *(const float2*)&Rp[off];
                v0 += r.x; v1 += r.y;
                *(float2*)&Cp[off] = make_float2(v0, v1);
            }
        }
    }
}

// ---------------------------------------------------------------------------
// Flash attention, fp16 m16n8k16, BM=64 (R10 config), cp.async double-buffered
// K/V, identity P C->A mapping. One block = (bh, 64-query tile), 4 warps.
// ---------------------------------------------------------------------------
#define HPAD 72                             // halves per smem row
#define TILE_H (64 * HPAD)                  // halves per tile
#define ATTN_SMEM_BYTES (4 * TILE_H * 2)    // 36864 B

__global__ void __launch_bounds__(128, 4) attn_h_kernel(
    const __half* __restrict__ qT, const __half* __restrict__ kT,
    const __half* __restrict__ vh, float* __restrict__ out)
{
    extern __shared__ __half hsm[];
    __half* Ks = hsm;                     // [2][64][HPAD]  (kT: [token][d])
    __half* Vs = hsm + 2 * TILE_H;        // [2][64][HPAD]  (v:  [d][token])
    const unsigned ks_u = (unsigned)__cvta_generic_to_shared(Ks);
    const unsigned vs_u = (unsigned)__cvta_generic_to_shared(Vs);

    const int tid  = threadIdx.x;
    const int w    = tid >> 5;
    const int lane = tid & 31;
    const int g    = lane >> 2;
    const int tig  = lane & 3;

    const int bh = blockIdx.y;
    const int qb = blockIdx.x * 64;

    const __half* qTp = qT + ((size_t)bh * NN + qb) * DD;
    const __half* kTp = kT + (size_t)bh * NN * DD;
    const __half* vp  = vh + (size_t)bh * DD * NN;

    // --- Stage Q tile into Ks buf0 via cp.async ---
    #pragma unroll
    for (int i = 0; i < 4; i++) {
        int lin = tid + i * 128;
        int row = lin >> 3, c = lin & 7;
        cpasync16(ks_u + (unsigned)((row * HPAD + c * 8) * 2),
                  qTp + (size_t)row * DD + c * 8);
    }
    cp_commit();
    cp_wait<0>();
    __syncthreads();

    unsigned qa[4][4];
    {
        const int m0 = w * 16 + g;
        #pragma unroll
        for (int kt = 0; kt < 4; kt++) {
            qa[kt][0] = *(const unsigned*)&Ks[(m0    ) * HPAD + kt * 16 + 2 * tig];
            qa[kt][1] = *(const unsigned*)&Ks[(m0 + 8) * HPAD + kt * 16 + 2 * tig];
            qa[kt][2] = *(const unsigned*)&Ks[(m0    ) * HPAD + kt * 16 + 2 * tig + 8];
            qa[kt][3] = *(const unsigned*)&Ks[(m0 + 8) * HPAD + kt * 16 + 2 * tig + 8];
        }
    }
    __syncthreads();

    // --- Pipeline prologue: tiles 0, 1 ---
    #pragma unroll
    for (int pre = 0; pre < 2; pre++) {
        int jt = pre * 64;
        unsigned kb = ks_u + (unsigned)(pre * TILE_H * 2);
        unsigned vb = vs_u + (unsigned)(pre * TILE_H * 2);
        #pragma unroll
        for (int i = 0; i < 4; i++) {
            int lin = tid + i * 128;
            int row = lin >> 3, c = lin & 7;
            cpasync16(kb + (unsigned)((row * HPAD + c * 8) * 2),
                      kTp + (size_t)(jt + row) * DD + c * 8);
            cpasync16(vb + (unsigned)((row * HPAD + c * 8) * 2),
                      vp + (size_t)row * NN + jt + c * 8);
        }
        cp_commit();
    }

    float O[8][4];
    #pragma unroll
    for (int t = 0; t < 8; t++)
        #pragma unroll
        for (int r = 0; r < 4; r++) O[t][r] = 0.f;
    float m0r = -INFINITY, m1r = -INFINITY, l0 = 0.f, l1 = 0.f;

    for (int it = 0; it < 64; it++) {
        const int cur = it & 1;
        const __half* Kc = Ks + cur * TILE_H;
        const __half* Vc = Vs + cur * TILE_H;

        if (it < 63) cp_wait<1>(); else cp_wait<0>();
        __syncthreads();

        // --- S = Q K^T ---
        float sc[8][4];
        #pragma unroll
        for (int t = 0; t < 8; t++) {
            sc[t][0] = sc[t][1] = sc[t][2] = sc[t][3] = 0.f;
            #pragma unroll
            for (int kt = 0; kt < 4; kt++) {
                unsigned b0 = *(const unsigned*)&Kc[(t * 8 + g) * HPAD + kt * 16 + 2 * tig];
                unsigned b1 = *(const unsigned*)&Kc[(t * 8 + g) * HPAD + kt * 16 + 2 * tig + 8];
                mma_f16(sc[t], qa[kt], b0, b1);
            }
        }

        // --- Online softmax ---
        float ml0 = -INFINITY, ml1 = -INFINITY;
        #pragma unroll
        for (int t = 0; t < 8; t++) {
            ml0 = fmaxf(ml0, fmaxf(sc[t][0], sc[t][1]));
            ml1 = fmaxf(ml1, fmaxf(sc[t][2], sc[t][3]));
        }
        ml0 = fmaxf(ml0, __shfl_xor_sync(0xffffffffu, ml0, 1));
        ml0 = fmaxf(ml0, __shfl_xor_sync(0xffffffffu, ml0, 2));
        ml1 = fmaxf(ml1, __shfl_xor_sync(0xffffffffu, ml1, 1));
        ml1 = fmaxf(ml1, __shfl_xor_sync(0xffffffffu, ml1, 2));

        const float mn0 = fmaxf(m0r, ml0);
        const float mn1 = fmaxf(m1r, ml1);
        const float corr0 = __expf(m0r - mn0);
        const float corr1 = __expf(m1r - mn1);
        m0r = mn0; m1r = mn1;

        unsigned pe[8], po[8];
        float ls0 = 0.f, ls1 = 0.f;
        #pragma unroll
        for (int t = 0; t < 8; t++) {
            float p0 = __expf(sc[t][0] - mn0);
            float p1 = __expf(sc[t][1] - mn0);
            float p2 = __expf(sc[t][2] - mn1);
            float p3 = __expf(sc[t][3] - mn1);
            ls0 += p0 + p1; ls1 += p2 + p3;
            pe[t] = packh2(p0, p1);
            po[t] = packh2(p2, p3);
        }
        ls0 += __shfl_xor_sync(0xffffffffu, ls0, 1);
        ls0 += __shfl_xor_sync(0xffffffffu, ls0, 2);
        ls1 += __shfl_xor_sync(0xffffffffu, ls1, 1);
        ls1 += __shfl_xor_sync(0xffffffffu, ls1, 2);
        l0 = l0 * corr0 + ls0;
        l1 = l1 * corr1 + ls1;

        #pragma unroll
        for (int t = 0; t < 8; t++) {
            O[t][0] *= corr0; O[t][1] *= corr0;
            O[t][2] *= corr1; O[t][3] *= corr1;
        }

        // --- O += P V^T : identity C->A mapping ---
        #pragma unroll
        for (int kn = 0; kn < 4; kn++) {
            unsigned pa[4];
            pa[0] = pe[2 * kn];
            pa[1] = po[2 * kn];
            pa[2] = pe[2 * kn + 1];
            pa[3] = po[2 * kn + 1];
            #pragma unroll
            for (int dt = 0; dt < 8; dt++) {
                unsigned b0 = *(const unsigned*)&Vc[(dt * 8 + g) * HPAD + kn * 16 + 2 * tig];
                unsigned b1 = *(const unsigned*)&Vc[(dt * 8 + g) * HPAD + kn * 16 + 2 * tig + 8];
                mma_f16(O[dt], pa, b0, b1);
            }
        }

        __syncthreads();

        if (it < 62) {
            int jt = (it + 2) * 64;
            unsigned kb = ks_u + (unsigned)(cur * TILE_H * 2);
            unsigned vb = vs_u + (unsigned)(cur * TILE_H * 2);
            #pragma unroll
            for (int i = 0; i < 4; i++) {
                int lin = tid + i * 128;
                int row = lin >> 3, c = lin & 7;
                cpasync16(kb + (unsigned)((row * HPAD + c * 8) * 2),
                          kTp + (size_t)(jt + row) * DD + c * 8);
                cpasync16(vb + (unsigned)((row * HPAD + c * 8) * 2),
                          vp + (size_t)row * NN + jt + c * 8);
            }
            cp_commit();
        }
    }

    // --- Epilogue ---
    const float inv0 = 1.f / l0;
    const float inv1 = 1.f / l1;
    const int b  = bh >> 2;
    const int hh = bh & 3;
    float* op = out + ((size_t)b * CC + hh * DD) * NN;
    const int tok0 = qb + w * 16 + g;
    const int tok1 = tok0 + 8;
    #pragma unroll
    for (int dt = 0; dt < 8; dt++) {
        int d = dt * 8 + 2 * tig;
        op[(size_t)d * NN + tok0]       = tf32r(O[dt][0] * inv0);
        op[(size_t)(d + 1) * NN + tok0] = tf32r(O[dt][1] * inv0);
        op[(size_t)d * NN + tok1]       = tf32r(O[dt][2] * inv1);
        op[(size_t)(d + 1) * NN + tok1] = tf32r(O[dt][3] * inv1);
    }
}

// ---------------------------------------------------------------------------
// Launch
// ---------------------------------------------------------------------------
extern "C" void kernel_launch(void* const* d_in, const int* in_sizes, int n_in,
                              void* d_out, int out_size)
{
    const float* x      = (const float*)d_in[0];
    const float* gn_w   = (const float*)d_in[1];
    const float* gn_b   = (const float*)d_in[2];
    const float* qkv_w  = (const float*)d_in[3];
    const float* qkv_b  = (const float*)d_in[4];
    const float* proj_w = (const float*)d_in[5];
    const float* proj_b = (const float*)d_in[6];
    float* out = (float*)d_out;

    void *p_xn, *p_att, *p_wq, *p_wp, *p_qT, *p_kT, *p_vh;
    cudaGetSymbolAddress(&p_xn,  g_xn);
    cudaGetSymbolAddress(&p_att, g_att);
    cudaGetSymbolAddress(&p_wq,  g_wq);
    cudaGetSymbolAddress(&p_wp,  g_wp);
    cudaGetSymbolAddress(&p_qT,  g_qT);
    cudaGetSymbolAddress(&p_kT,  g_kT);
    cudaGetSymbolAddress(&p_vh,  g_vh);
    float*  xn  = (float*)p_xn;
    float*  att = (float*)p_att;
    float*  wq  = (float*)p_wq;
    float*  wp  = (float*)p_wp;
    __half* qT  = (__half*)p_qT;
    __half* kT  = (__half*)p_kT;
    __half* vh  = (__half*)p_vh;

    cudaFuncSetAttribute(attn_h_kernel,
                         cudaFuncAttributeMaxDynamicSharedMemorySize,
                         ATTN_SMEM_BYTES);

    // 0. Round weights to tf32 (also zeros gn stats)
    wconv_kernel<<<(3 * CC * CC + 255) / 256, 256>>>(qkv_w, proj_w, wq, wp);

    // 1. GroupNorm: stats (atomic) then normalize
    gn_stats_kernel<<<BB * GG * 8, 256>>>(x);
    gn_norm_kernel<<<BB * CC * NN / 4 / 4096, 256>>>(x, gn_w, gn_b, xn);

    // 2. QKV GEMM with fused pack epilogue (writes qT/kT/vh halves directly)
    {
        dim3 grid(NN / 128, (3 * CC) / 64, BB);
        gemm_qkv_kernel<<<grid, 256>>>(wq, xn, qkv_b, qT, kT, vh);
    }

    // 3. Attention (fp16 tensor, BM=64, cp.async pipeline)
    {
        dim3 grid(NN / 64, BB * NHEAD);
        attn_h_kernel<<<grid, 128, ATTN_SMEM_BYTES>>>(qT, kT, vh, att);
    }

    // 4. Proj GEMM (tf32 tensor, cp.async pipeline) + bias + residual
    {
        dim3 grid(NN / 128, CC / 64, BB);
        gemm_tf32_kernel<<<grid, 256>>>(wp, att, proj_b, x, out, CC);
    }
}

// round 14
// speedup vs baseline: 1.1546x; 1.0692x over previous
#include <cuda_runtime.h>
#include <cuda_fp16.h>
#include <math.h>

// Problem constants
#define BB    4
#define CC    256
#define NN    4096      // h*w = 64*64
#define GG    8
#define NHEAD 4
#define DD    64        // head dim
#define EPSV  1e-5f
#define LOG2E 1.4426950408889634f

// Scratch (device globals: no allocations allowed)
__device__ float  g_att[(size_t)BB * CC * NN];          // attention output (tf32-rounded)
__device__ float  g_wq [(size_t)BB * 3 * CC * CC];      // per-batch GN-folded qkv weights (tf32)
__device__ float  g_wqb[(size_t)BB * 3 * CC];           // per-batch effective qkv bias
__device__ float  g_wp [(size_t)CC * CC];               // proj_w tf32-rounded
__device__ float  g_stats[BB * GG * 2];                 // gn partial sums
__device__ __half g_qT[(size_t)BB * NHEAD * NN * DD];   // Q^T half [bh][tok][d] (prescaled, log2 domain)
__device__ __half g_kT[(size_t)BB * NHEAD * NN * DD];   // K^T half [bh][tok][d]
__device__ __half g_vh[(size_t)BB * NHEAD * DD * NN];   // V half [bh][d][tok]

__device__ __forceinline__ unsigned f2tf32(float x) {
    unsigned r;
    asm("cvt.rna.tf32.f32 %0, %1;" : "=r"(r) : "f"(x));
    return r;
}
__device__ __forceinline__ float tf32r(float x) {
    return __uint_as_float(f2tf32(x));
}
__device__ __forceinline__ float ex2(float x) {
    float r;
    asm("ex2.approx.ftz.f32 %0, %1;" : "=f"(r) : "f"(x));
    return r;
}

__device__ __forceinline__ void mma_tf32(float c[4], const unsigned a[4],
                                         unsigned b0, unsigned b1) {
    asm volatile(
        "mma.sync.aligned.m16n8k8.row.col.f32.tf32.tf32.f32 "
        "{%0,%1,%2,%3}, {%4,%5,%6,%7}, {%8,%9}, {%0,%1,%2,%3};"
        : "+f"(c[0]), "+f"(c[1]), "+f"(c[2]), "+f"(c[3])
        : "r"(a[0]), "r"(a[1]), "r"(a[2]), "r"(a[3]), "r"(b0), "r"(b1));
}

__device__ __forceinline__ void mma_f16(float c[4], const unsigned a[4],
                                        unsigned b0, unsigned b1) {
    asm volatile(
        "mma.sync.aligned.m16n8k16.row.col.f32.f16.f16.f32 "
        "{%0,%1,%2,%3}, {%4,%5,%6,%7}, {%8,%9}, {%0,%1,%2,%3};"
        : "+f"(c[0]), "+f"(c[1]), "+f"(c[2]), "+f"(c[3])
        : "r"(a[0]), "r"(a[1]), "r"(a[2]), "r"(a[3]), "r"(b0), "r"(b1));
}

__device__ __forceinline__ void cpasync16(unsigned saddr, const void* gptr) {
    asm volatile("cp.async.cg.shared.global [%0], [%1], 16;"
                 :: "r"(saddr), "l"(gptr));
}
__device__ __forceinline__ void cp_commit() {
    asm volatile("cp.async.commit_group;");
}
template <int N>
__device__ __forceinline__ void cp_wait() {
    asm volatile("cp.async.wait_group %0;" :: "n"(N));
}
__device__ __forceinline__ unsigned packh2(float a, float b) {
    __half2 h = __floats2half2_rn(a, b);
    return *(const unsigned*)&h;
}

// ---------------------------------------------------------------------------
// Weight conversion: round proj_w to tf32, zero gn stats.
// ---------------------------------------------------------------------------
__global__ __launch_bounds__(256) void wconv_kernel(
    const float* __restrict__ proj_w, float* __restrict__ wp)
{
    int i = blockIdx.x * 256 + threadIdx.x;
    if (blockIdx.x == 0 && threadIdx.x < BB * GG * 2) g_stats[threadIdx.x] = 0.f;
    if (i < CC * CC) wp[i] = tf32r(proj_w[i]);
}

// ---------------------------------------------------------------------------
// GroupNorm stats: 8 blocks per (b,g), atomic partial sums.
// ---------------------------------------------------------------------------
__global__ __launch_bounds__(256) void gn_stats_kernel(const float* __restrict__ x)
{
    const int bg   = blockIdx.x >> 3;
    const int part = blockIdx.x & 7;
    const float4* xp = (const float4*)(x) + (size_t)bg * 32768 + part * 4096;

    float s = 0.f, ss = 0.f;
    #pragma unroll
    for (int i = 0; i < 16; i++) {
        float4 v = xp[i * 256 + threadIdx.x];
        s  += v.x + v.y + v.z + v.w;
        ss += v.x * v.x + v.y * v.y + v.z * v.z + v.w * v.w;
    }
    __shared__ float rs[8], rss[8];
    #pragma unroll
    for (int o = 16; o; o >>= 1) {
        s  += __shfl_down_sync(0xffffffffu, s,  o);
        ss += __shfl_down_sync(0xffffffffu, ss, o);
    }
    int wid = threadIdx.x >> 5, lid = threadIdx.x & 31;
    if (!lid) { rs[wid] = s; rss[wid] = ss; }
    __syncthreads();
    if (threadIdx.x < 8) {
        s = rs[threadIdx.x]; ss = rss[threadIdx.x];
        #pragma unroll
        for (int o = 4; o; o >>= 1) {
            s  += __shfl_down_sync(0xffu, s,  o);
            ss += __shfl_down_sync(0xffu, ss, o);
        }
        if (threadIdx.x == 0) {
            atomicAdd(&g_stats[bg * 2],     s);
            atomicAdd(&g_stats[bg * 2 + 1], ss);
        }
    }
}

// ---------------------------------------------------------------------------
// GN-fold weight generation: W'[b][o][c] = tf32(W[o][c] * a[b][c]),
// bias'[b][o] = qkv_b[o] + sum_c W[o][c] * shift[b][c].
// One block per (o, b); 256 threads = channels.
// ---------------------------------------------------------------------------
__global__ __launch_bounds__(256) void wgen_kernel(
    const float* __restrict__ qkv_w, const float* __restrict__ qkv_b,
    const float* __restrict__ gw, const float* __restrict__ gb,
    float* __restrict__ wq, float* __restrict__ wqb)
{
    const int o = blockIdx.x;        // 0..767
    const int b = blockIdx.y;        // 0..3
    const int c = threadIdx.x;       // 0..255
    const int bg = b * GG + (c >> 5);

    const float s  = g_stats[bg * 2];
    const float ss = g_stats[bg * 2 + 1];
    const float mean = s * (1.f / 131072.f);
    const float var  = ss * (1.f / 131072.f) - mean * mean;
    const float rstd = rsqrtf(var + EPSV);
    const float a     = gw[c] * rstd;
    const float shift = gb[c] - mean * a;

    const float wv = qkv_w[o * CC + c];
    wq[((size_t)(b * 3 * CC + o)) * CC + c] = tf32r(wv * a);

    float p = wv * shift;
    __shared__ float red[8];
    #pragma unroll
    for (int off = 16; off; off >>= 1) p += __shfl_down_sync(0xffffffffu, p, off);
    if ((c & 31) == 0) red[c >> 5] = p;
    __syncthreads();
    if (c < 8) {
        p = red[c];
        #pragma unroll
        for (int off = 4; off; off >>= 1) p += __shfl_down_sync(0xffu, p, off);
        if (c == 0) wqb[b * 3 * CC + o] = qkv_b[o] + p;
    }
}

// ---------------------------------------------------------------------------
// QKV GEMM (tf32 MMA, cp.async double-buffered) on RAW x with GN-folded
// per-batch weights; FUSED pack epilogue -> qT/kT/vh halves.
// Q prescale = 0.125 * log2(e)  (attention softmax in base-2 domain).
// ---------------------------------------------------------------------------
__global__ __launch_bounds__(256) void gemm_qkv_kernel(
    const float* __restrict__ Wq, const float* __restrict__ x,
    const float* __restrict__ Wqb,
    __half* __restrict__ qT, __half* __restrict__ kT, __half* __restrict__ vh)
{
    __shared__ float As[2][64][36];
    __shared__ float Bs[2][32][132];
    const unsigned as_u = (unsigned)__cvta_generic_to_shared(&As[0][0][0]);
    const unsigned bs_u = (unsigned)__cvta_generic_to_shared(&Bs[0][0][0]);

    const int bz = blockIdx.z;
    const float* A    = Wq  + (size_t)bz * 3 * CC * CC;
    const float* bias = Wqb + (size_t)bz * 3 * CC;
    const float* Bp   = x   + (size_t)bz * CC * NN;

    const int n0 = blockIdx.x * 128;
    const int m0 = blockIdx.y * 64;
    const int tid = threadIdx.x;
    const int w = tid >> 5, lane = tid & 31;
    const int g = lane >> 2, tig = lane & 3;
    const int wm = (w >> 2) * 32;
    const int wn = (w & 3) * 32;

    const int ar = tid >> 3, ac4 = tid & 7;
    const int br = tid >> 5, bc4 = tid & 31;

    #define GEMM_ISSUE(K0, BUF)                                              \
    {                                                                        \
        unsigned ab = as_u + (unsigned)((BUF) * 64 * 36 * 4);                \
        unsigned bb = bs_u + (unsigned)((BUF) * 32 * 132 * 4);               \
        _Pragma("unroll")                                                    \
        for (int i = 0; i < 2; i++) {                                        \
            int r = ar + i * 32;                                             \
            cpasync16(ab + (unsigned)((r * 36 + ac4 * 4) * 4),               \
                      &A[(size_t)(m0 + r) * CC + (K0) + ac4 * 4]);           \
        }                                                                    \
        _Pragma("unroll")                                                    \
        for (int i = 0; i < 4; i++) {                                        \
            int r = br + i * 8;                                              \
            cpasync16(bb + (unsigned)((r * 132 + bc4 * 4) * 4),              \
                      &Bp[(size_t)((K0) + r) * NN + n0 + bc4 * 4]);          \
        }                                                                    \
        cp_commit();                                                         \
    }

    GEMM_ISSUE(0, 0)
    GEMM_ISSUE(32, 1)

    float acc[2][4][4] = {};

    for (int kt = 0; kt < 8; kt++) {
        const int cur = kt & 1;
        if (kt < 7) cp_wait<1>(); else cp_wait<0>();
        __syncthreads();

        #pragma unroll
        for (int ks = 0; ks < 4; ks++) {
            unsigned a[2][4];
            #pragma unroll
            for (int mt = 0; mt < 2; mt++) {
                a[mt][0] = __float_as_uint(As[cur][wm + mt * 16 + g    ][ks * 8 + tig]);
                a[mt][1] = __float_as_uint(As[cur][wm + mt * 16 + g + 8][ks * 8 + tig]);
                a[mt][2] = __float_as_uint(As[cur][wm + mt * 16 + g    ][ks * 8 + tig + 4]);
                a[mt][3] = __float_as_uint(As[cur][wm + mt * 16 + g + 8][ks * 8 + tig + 4]);
            }
            #pragma unroll
            for (int nt = 0; nt < 4; nt++) {
                unsigned b0 = __float_as_uint(Bs[cur][ks * 8 + tig    ][wn + nt * 8 + g]);
                unsigned b1 = __float_as_uint(Bs[cur][ks * 8 + tig + 4][wn + nt * 8 + g]);
                mma_tf32(acc[0][nt], a[0], b0, b1);
                mma_tf32(acc[1][nt], a[1], b0, b1);
            }
        }
        __syncthreads();

        if (kt < 6) GEMM_ISSUE((kt + 2) * 32, cur)
    }
    #undef GEMM_ISSUE

    // --- Fused pack epilogue ---
    const int which = m0 >> 8;            // 0=Q, 1=K, 2=V
    const int hh    = (m0 >> 6) & 3;
    const int bh    = bz * NHEAD + hh;
    const float scale = (which == 0) ? 0.125f * LOG2E : 1.f;

    if (which == 2) {
        // V: natural [d][tok] layout, direct half2 stores
        #pragma unroll
        for (int mt = 0; mt < 2; mt++) {
            #pragma unroll
            for (int half = 0; half < 2; half++) {
                const int d = wm + mt * 16 + g + half * 8;
                const float bi = bias[m0 + d];
                #pragma unroll
                for (int nt = 0; nt < 4; nt++) {
                    float v0 = acc[mt][nt][half * 2 + 0] + bi;
                    float v1 = acc[mt][nt][half * 2 + 1] + bi;
                    const size_t off = (size_t)(bh * DD + d) * NN + n0 + wn + nt * 8 + 2 * tig;
                    *(__half2*)&vh[off] = __floats2half2_rn(v0, v1);
                }
            }
        }
    } else {
        // Q/K: transpose through smem (reuse As as [128][72] halves)
        __half* tsh = (__half*)&As[0][0][0];
        #pragma unroll
        for (int mt = 0; mt < 2; mt++) {
            #pragma unroll
            for (int half = 0; half < 2; half++) {
                const int d = wm + mt * 16 + g + half * 8;
                const float bi = bias[m0 + d];
                #pragma unroll
                for (int nt = 0; nt < 4; nt++) {
                    float v0 = (acc[mt][nt][half * 2 + 0] + bi) * scale;
                    float v1 = (acc[mt][nt][half * 2 + 1] + bi) * scale;
                    const int tok = wn + nt * 8 + 2 * tig;
                    tsh[tok * 72 + d]       = __float2half_rn(v0);
                    tsh[(tok + 1) * 72 + d] = __float2half_rn(v1);
                }
            }
        }
        __syncthreads();
        __half* dst = (which ? kT : qT) + ((size_t)bh * NN + n0) * DD;
        #pragma unroll
        for (int i = 0; i < 4; i++) {
            int lin = tid + i * 256;
            int row = lin >> 3, c = lin & 7;
            *(uint4*)&dst[(size_t)row * DD + c * 8] =
                *(const uint4*)&tsh[row * 72 + c * 8];
        }
    }
}

// ---------------------------------------------------------------------------
// Proj GEMM: tf32 MMA with cp.async double-buffering (fp32 out + residual).
// ---------------------------------------------------------------------------
__global__ __launch_bounds__(256) void gemm_tf32_kernel(
    const float* __restrict__ A, const float* __restrict__ Bm,
    const float* __restrict__ bias, const float* __restrict__ res,
    float* __restrict__ C, int M)
{
    __shared__ float As[2][64][36];
    __shared__ float Bs[2][32][132];
    const unsigned as_u = (unsigned)__cvta_generic_to_shared(&As[0][0][0]);
    const unsigned bs_u = (unsigned)__cvta_generic_to_shared(&Bs[0][0][0]);

    const int bz = blockIdx.z;
    const float* Bp = Bm + (size_t)bz * CC * NN;
    float*       Cp = C  + (size_t)bz * M * NN;
    const float* Rp = res + (size_t)bz * M * NN;

    const int n0 = blockIdx.x * 128;
    const int m0 = blockIdx.y * 64;
    const int tid = threadIdx.x;
    const int w = tid >> 5, lane = tid & 31;
    const int g = lane >> 2, tig = lane & 3;
    const int wm = (w >> 2) * 32;
    const int wn = (w & 3) * 32;

    const int ar = tid >> 3, ac4 = tid & 7;
    const int br = tid >> 5, bc4 = tid & 31;

    #define GEMM_ISSUE(K0, BUF)                                              \
    {                                                                        \
        unsigned ab = as_u + (unsigned)((BUF) * 64 * 36 * 4);                \
        unsigned bb = bs_u + (unsigned)((BUF) * 32 * 132 * 4);               \
        _Pragma("unroll")                                                    \
        for (int i = 0; i < 2; i++) {                                        \
            int r = ar + i * 32;                                             \
            cpasync16(ab + (unsigned)((r * 36 + ac4 * 4) * 4),               \
                      &A[(size_t)(m0 + r) * CC + (K0) + ac4 * 4]);           \
        }                                                                    \
        _Pragma("unroll")                                                    \
        for (int i = 0; i < 4; i++) {                                        \
            int r = br + i * 8;                                              \
            cpasync16(bb + (unsigned)((r * 132 + bc4 * 4) * 4),              \
                      &Bp[(size_t)((K0) + r) * NN + n0 + bc4 * 4]);          \
        }                                                                    \
        cp_commit();                                                         \
    }

    GEMM_ISSUE(0, 0)
    GEMM_ISSUE(32, 1)

    float acc[2][4][4] = {};

    for (int kt = 0; kt < 8; kt++) {
        const int cur = kt & 1;
        if (kt < 7) cp_wait<1>(); else cp_wait<0>();
        __syncthreads();

        #pragma unroll
        for (int ks = 0; ks < 4; ks++) {
            unsigned a[2][4];
            #pragma unroll
            for (int mt = 0; mt < 2; mt++) {
                a[mt][0] = __float_as_uint(As[cur][wm + mt * 16 + g    ][ks * 8 + tig]);
                a[mt][1] = __float_as_uint(As[cur][wm + mt * 16 + g + 8][ks * 8 + tig]);
                a[mt][2] = __float_as_uint(As[cur][wm + mt * 16 + g    ][ks * 8 + tig + 4]);
                a[mt][3] = __float_as_uint(As[cur][wm + mt * 16 + g + 8][ks * 8 + tig + 4]);
            }
            #pragma unroll
            for (int nt = 0; nt < 4; nt++) {
                unsigned b0 = __float_as_uint(Bs[cur][ks * 8 + tig    ][wn + nt * 8 + g]);
                unsigned b1 = __float_as_uint(Bs[cur][ks * 8 + tig + 4][wn + nt * 8 + g]);
                mma_tf32(acc[0][nt], a[0], b0, b1);
                mma_tf32(acc[1][nt], a[1], b0, b1);
            }
        }
        __syncthreads();

        if (kt < 6) GEMM_ISSUE((kt + 2) * 32, cur)
    }
    #undef GEMM_ISSUE

    #pragma unroll
    for (int mt = 0; mt < 2; mt++) {
        #pragma unroll
        for (int half = 0; half < 2; half++) {
            const int m = m0 + wm + mt * 16 + g + half * 8;
            const float bi = bias[m];
            #pragma unroll
            for (int nt = 0; nt < 4; nt++) {
                float v0 = acc[mt][nt][half * 2 + 0] + bi;
                float v1 = acc[mt][nt][half * 2 + 1] + bi;
                const size_t off = (size_t)m * NN + n0 + wn + nt * 8 + 2 * tig;
                float2 r = *(const float2*)&Rp[off];
                v0 += r.x; v1 += r.y;
                *(float2*)&Cp[off] = make_float2(v0, v1);
            }
        }
    }
}

// ---------------------------------------------------------------------------
// Flash attention, fp16 m16n8k16, BM=64, cp.async double-buffered K/V,
// identity P C->A mapping, base-2 softmax (logits arrive pre-scaled by log2e).
// One block = (bh, 64-query tile), 4 warps.
// ---------------------------------------------------------------------------
#define HPAD 72                             // halves per smem row
#define TILE_H (64 * HPAD)                  // halves per tile
#define ATTN_SMEM_BYTES (4 * TILE_H * 2)    // 36864 B

__global__ void __launch_bounds__(128, 4) attn_h_kernel(
    const __half* __restrict__ qT, const __half* __restrict__ kT,
    const __half* __restrict__ vh, float* __restrict__ out)
{
    extern __shared__ __half hsm[];
    __half* Ks = hsm;                     // [2][64][HPAD]  (kT: [token][d])
    __half* Vs = hsm + 2 * TILE_H;        // [2][64][HPAD]  (v:  [d][token])
    const unsigned ks_u = (unsigned)__cvta_generic_to_shared(Ks);
    const unsigned vs_u = (unsigned)__cvta_generic_to_shared(Vs);

    const int tid  = threadIdx.x;
    const int w    = tid >> 5;
    const int lane = tid & 31;
    const int g    = lane >> 2;
    const int tig  = lane & 3;

    const int bh = blockIdx.y;
    const int qb = blockIdx.x * 64;

    const __half* qTp = qT + ((size_t)bh * NN + qb) * DD;
    const __half* kTp = kT + (size_t)bh * NN * DD;
    const __half* vp  = vh + (size_t)bh * DD * NN;

    // --- Stage Q tile into Ks buf0 via cp.async ---
    #pragma unroll
    for (int i = 0; i < 4; i++) {
        int lin = tid + i * 128;
        int row = lin >> 3, c = lin & 7;
        cpasync16(ks_u + (unsigned)((row * HPAD + c * 8) * 2),
                  qTp + (size_t)row * DD + c * 8);
    }
    cp_commit();
    cp_wait<0>();
    __syncthreads();

    unsigned qa[4][4];
    {
        const int m0 = w * 16 + g;
        #pragma unroll
        for (int kt = 0; kt < 4; kt++) {
            qa[kt][0] = *(const unsigned*)&Ks[(m0    ) * HPAD + kt * 16 + 2 * tig];
            qa[kt][1] = *(const unsigned*)&Ks[(m0 + 8) * HPAD + kt * 16 + 2 * tig];
            qa[kt][2] = *(const unsigned*)&Ks[(m0    ) * HPAD + kt * 16 + 2 * tig + 8];
            qa[kt][3] = *(const unsigned*)&Ks[(m0 + 8) * HPAD + kt * 16 + 2 * tig + 8];
        }
    }
    __syncthreads();

    // --- Pipeline prologue: tiles 0, 1 ---
    #pragma unroll
    for (int pre = 0; pre < 2; pre++) {
        int jt = pre * 64;
        unsigned kb = ks_u + (unsigned)(pre * TILE_H * 2);
        unsigned vb = vs_u + (unsigned)(pre * TILE_H * 2);
        #pragma unroll
        for (int i = 0; i < 4; i++) {
            int lin = tid + i * 128;
            int row = lin >> 3, c = lin & 7;
            cpasync16(kb + (unsigned)((row * HPAD + c * 8) * 2),
                      kTp + (size_t)(jt + row) * DD + c * 8);
            cpasync16(vb + (unsigned)((row * HPAD + c * 8) * 2),
                      vp + (size_t)row * NN + jt + c * 8);
        }
        cp_commit();
    }

    float O[8][4];
    #pragma unroll
    for (int t = 0; t < 8; t++)
        #pragma unroll
        for (int r = 0; r < 4; r++) O[t][r] = 0.f;
    float m0r = -INFINITY, m1r = -INFINITY, l0 = 0.f, l1 = 0.f;

    for (int it = 0; it < 64; it++) {
        const int cur = it & 1;
        const __half* Kc = Ks + cur * TILE_H;
        const __half* Vc = Vs + cur * TILE_H;

        if (it < 63) cp_wait<1>(); else cp_wait<0>();
        __syncthreads();

        // --- S = Q K^T (log2-domain logits) ---
        float sc[8][4];
        #pragma unroll
        for (int t = 0; t < 8; t++) {
            sc[t][0] = sc[t][1] = sc[t][2] = sc[t][3] = 0.f;
            #pragma unroll
            for (int kt = 0; kt < 4; kt++) {
                unsigned b0 = *(const unsigned*)&Kc[(t * 8 + g) * HPAD + kt * 16 + 2 * tig];
                unsigned b1 = *(const unsigned*)&Kc[(t * 8 + g) * HPAD + kt * 16 + 2 * tig + 8];
                mma_f16(sc[t], qa[kt], b0, b1);
            }
        }

        // --- Online softmax (base-2) ---
        float ml0 = -INFINITY, ml1 = -INFINITY;
        #pragma unroll
        for (int t = 0; t < 8; t++) {
            ml0 = fmaxf(ml0, fmaxf(sc[t][0], sc[t][1]));
            ml1 = fmaxf(ml1, fmaxf(sc[t][2], sc[t][3]));
        }
        ml0 = fmaxf(ml0, __shfl_xor_sync(0xffffffffu, ml0, 1));
        ml0 = fmaxf(ml0, __shfl_xor_sync(0xffffffffu, ml0, 2));
        ml1 = fmaxf(ml1, __shfl_xor_sync(0xffffffffu, ml1, 1));
        ml1 = fmaxf(ml1, __shfl_xor_sync(0xffffffffu, ml1, 2));

        const float mn0 = fmaxf(m0r, ml0);
        const float mn1 = fmaxf(m1r, ml1);
        const float corr0 = ex2(m0r - mn0);
        const float corr1 = ex2(m1r - mn1);
        m0r = mn0; m1r = mn1;

        unsigned pe[8], po[8];
        float ls0 = 0.f, ls1 = 0.f;
        #pragma unroll
        for (int t = 0; t < 8; t++) {
            float p0 = ex2(sc[t][0] - mn0);
            float p1 = ex2(sc[t][1] - mn0);
            float p2 = ex2(sc[t][2] - mn1);
            float p3 = ex2(sc[t][3] - mn1);
            ls0 += p0 + p1; ls1 += p2 + p3;
            pe[t] = packh2(p0, p1);
            po[t] = packh2(p2, p3);
        }
        ls0 += __shfl_xor_sync(0xffffffffu, ls0, 1);
        ls0 += __shfl_xor_sync(0xffffffffu, ls0, 2);
        ls1 += __shfl_xor_sync(0xffffffffu, ls1, 1);
        ls1 += __shfl_xor_sync(0xffffffffu, ls1, 2);
        l0 = l0 * corr0 + ls0;
        l1 = l1 * corr1 + ls1;

        #pragma unroll
        for (int t = 0; t < 8; t++) {
            O[t][0] *= corr0; O[t][1] *= corr0;
            O[t][2] *= corr1; O[t][3] *= corr1;
        }

        // --- O += P V^T : identity C->A mapping ---
        #pragma unroll
        for (int kn = 0; kn < 4; kn++) {
            unsigned pa[4];
            pa[0] = pe[2 * kn];
            pa[1] = po[2 * kn];
            pa[2] = pe[2 * kn + 1];
            pa[3] = po[2 * kn + 1];
            #pragma unroll
            for (int dt = 0; dt < 8; dt++) {
                unsigned b0 = *(const unsigned*)&Vc[(dt * 8 + g) * HPAD + kn * 16 + 2 * tig];
                unsigned b1 = *(const unsigned*)&Vc[(dt * 8 + g) * HPAD + kn * 16 + 2 * tig + 8];
                mma_f16(O[dt], pa, b0, b1);
            }
        }

        __syncthreads();

        if (it < 62) {
            int jt = (it + 2) * 64;
            unsigned kb = ks_u + (unsigned)(cur * TILE_H * 2);
            unsigned vb = vs_u + (unsigned)(cur * TILE_H * 2);
            #pragma unroll
            for (int i = 0; i < 4; i++) {
                int lin = tid + i * 128;
                int row = lin >> 3, c = lin & 7;
                cpasync16(kb + (unsigned)((row * HPAD + c * 8) * 2),
                          kTp + (size_t)(jt + row) * DD + c * 8);
                cpasync16(vb + (unsigned)((row * HPAD + c * 8) * 2),
                          vp + (size_t)row * NN + jt + c * 8);
            }
            cp_commit();
        }
    }

    // --- Epilogue ---
    const float inv0 = 1.f / l0;
    const float inv1 = 1.f / l1;
    const int b  = bh >> 2;
    const int hh = bh & 3;
    float* op = out + ((size_t)b * CC + hh * DD) * NN;
    const int tok0 = qb + w * 16 + g;
    const int tok1 = tok0 + 8;
    #pragma unroll
    for (int dt = 0; dt < 8; dt++) {
        int d = dt * 8 + 2 * tig;
        op[(size_t)d * NN + tok0]       = tf32r(O[dt][0] * inv0);
        op[(size_t)(d + 1) * NN + tok0] = tf32r(O[dt][1] * inv0);
        op[(size_t)d * NN + tok1]       = tf32r(O[dt][2] * inv1);
        op[(size_t)(d + 1) * NN + tok1] = tf32r(O[dt][3] * inv1);
    }
}

// ---------------------------------------------------------------------------
// Launch
// ---------------------------------------------------------------------------
extern "C" void kernel_launch(void* const* d_in, const int* in_sizes, int n_in,
                              void* d_out, int out_size)
{
    const float* x      = (const float*)d_in[0];
    const float* gn_w   = (const float*)d_in[1];
    const float* gn_b   = (const float*)d_in[2];
    const float* qkv_w  = (const float*)d_in[3];
    const float* qkv_b  = (const float*)d_in[4];
    const float* proj_w = (const float*)d_in[5];
    const float* proj_b = (const float*)d_in[6];
    float* out = (float*)d_out;

    void *p_att, *p_wq, *p_wqb, *p_wp, *p_qT, *p_kT, *p_vh;
    cudaGetSymbolAddress(&p_att, g_att);
    cudaGetSymbolAddress(&p_wq,  g_wq);
    cudaGetSymbolAddress(&p_wqb, g_wqb);
    cudaGetSymbolAddress(&p_wp,  g_wp);
    cudaGetSymbolAddress(&p_qT,  g_qT);
    cudaGetSymbolAddress(&p_kT,  g_kT);
    cudaGetSymbolAddress(&p_vh,  g_vh);
    float*  att = (float*)p_att;
    float*  wq  = (float*)p_wq;
    float*  wqb = (float*)p_wqb;
    float*  wp  = (float*)p_wp;
    __half* qT  = (__half*)p_qT;
    __half* kT  = (__half*)p_kT;
    __half* vh  = (__half*)p_vh;

    cudaFuncSetAttribute(attn_h_kernel,
                         cudaFuncAttributeMaxDynamicSharedMemorySize,
                         ATTN_SMEM_BYTES);

    // 0. Round proj weights to tf32 (also zeros gn stats)
    wconv_kernel<<<(CC * CC + 255) / 256, 256>>>(proj_w, wp);

    // 1. GroupNorm stats (atomic partial sums)
    gn_stats_kernel<<<BB * GG * 8, 256>>>(x);

    // 1b. GN-folded per-batch qkv weights + effective bias
    {
        dim3 grid(3 * CC, BB);
        wgen_kernel<<<grid, 256>>>(qkv_w, qkv_b, gn_w, gn_b, wq, wqb);
    }

    // 2. QKV GEMM on raw x with fused pack epilogue
    {
        dim3 grid(NN / 128, (3 * CC) / 64, BB);
        gemm_qkv_kernel<<<grid, 256>>>(wq, x, wqb, qT, kT, vh);
    }

    // 3. Attention (fp16 tensor, BM=64, cp.async pipeline, base-2 softmax)
    {
        dim3 grid(NN / 64, BB * NHEAD);
        attn_h_kernel<<<grid, 128, ATTN_SMEM_BYTES>>>(qT, kT, vh, att);
    }

    // 4. Proj GEMM (tf32 tensor, cp.async pipeline) + bias + residual
    {
        dim3 grid(NN / 128, CC / 64, BB);
        gemm_tf32_kernel<<<grid, 256>>>(wp, att, proj_b, x, out, CC);
    }
}